// round 16
// baseline (speedup 1.0000x reference)
#include <cuda_runtime.h>

#define KK    64
#define S1C   5
#define CC    128
#define MM    320         // KK*S1C
#define PP    1936        // 44*44
#define NN    8
#define PT    128         // pixels per tile
#define TILES 16          // ceil(1936/128)
#define NBLK  128         // grid size (fully co-resident: 128 < 148 SMs)
#define ALPHA_C 1500.0f
#define EPS_C   1e-12f

// ---- device scratch (static: no allocations allowed) ----
__device__ float g_part[NN * TILES * 2 * KK * CC];  // per-(tile,pixel-half) partials (8.4 MB)
__device__ float g_sumw[NN * TILES * 128];          // per-(tile, k, ph)
__device__ int g_cnt[NN];                           // per-n progress: 16 tiles -> 24 finalize -> reset 0

// ---- f32x2 helpers (ptxas never auto-emits FFMA2) ----
__device__ __forceinline__ unsigned long long dup2(float v) {
    unsigned long long r;
    asm("mov.b64 %0, {%1, %1};" : "=l"(r) : "f"(v));
    return r;
}
__device__ __forceinline__ void fma2(unsigned long long& d, unsigned long long a, unsigned long long b) {
    asm("fma.rn.f32x2 %0, %1, %2, %0;" : "+l"(d) : "l"(a), "l"(b));
}
__device__ __forceinline__ float2 unpack2(unsigned long long v) {
    float2 r;
    asm("mov.b64 {%0, %1}, %2;" : "=f"(r.x), "=f"(r.y) : "l"(v));
    return r;
}

// ======================= single fused kernel =======================
// block = (n, pixel-tile of 128), 128 blocks = 1 co-resident wave, 1024 threads (8 warps/SMSP).
// smem 158464 B:
//   xs : [64 c2][130 p][2]  pairs {x[2c2][p], x[2c2+1][p]}    66560 B
//   ws : 80 pairs x 256     one 80 KB w chunk / was alias     81920 B
//   red: [128 p][17]        cross-warp alpha reduction         8704 B
//   bs : float[320]         biases                             1280 B
__global__ __launch_bounds__(1024, 1)
void main_kernel(const float* __restrict__ x, const float* __restrict__ cent,
                 float* __restrict__ sa_out, float* __restrict__ out) {
    extern __shared__ float smem[];
    float* xs  = smem;                    // 16640 floats
    float* ws  = smem + 16640;            // 20480 floats (alias: was 64x130x2 = 16640)
    float* red = smem + 16640 + 20480;    // 2176 floats
    float* bs  = red + 2176;              // 320 floats
    float* was = ws;

    int tid = threadIdx.x;
    int lane = tid & 31;
    int wid = tid >> 5;           // 32 warps
    int mg = wid & 15;            // k-pair base within chunk
    int ph = wid >> 4;            // pixel half (0: p<64, 1: p>=64)
    int bx = blockIdx.x;
    int n = bx >> 4, tile = bx & 15;
    int p0t = tile * PT;
    int pvalid = min(PT, PP - p0t);   // 128, or 16 on tile 15

    // thread's 2 pixels
    int p0 = ph * 64 + 2 * lane;      // pixels p0, p0+1

    // ---- load x tile: pair-interleave in registers, STS.128 stores ----
    {
        int c2 = tid >> 4;               // 64 rows of c-pairs
        int seg = (tid & 15) * 8;        // 8-pixel segment
        const float* s0 = x + (n * CC + 2 * c2) * PP + p0t + seg;
        const float* s1 = s0 + PP;
        bool ok = seg < pvalid;
        #pragma unroll
        for (int i = 0; i < 2; i++) {
            float4 a = ok ? *(const float4*)(s0 + i * 4) : make_float4(0.f, 0.f, 0.f, 0.f);
            float4 b = ok ? *(const float4*)(s1 + i * 4) : make_float4(0.f, 0.f, 0.f, 0.f);
            float* d = xs + (c2 * 130 + seg + i * 4) * 2;
            *(float4*)(d)     = make_float4(a.x, b.x, a.y, b.y);
            *(float4*)(d + 4) = make_float4(a.z, b.z, a.w, b.w);
        }
    }

    // ---- phase 1: logits GEMM (2 chunks of 32 k x 5 s) + register softmax over s ----
    float l0r[8], btr[8];   // idx = ch*4 + k2*2 + px ; k = ch*32 + mg + k2*16 ; p = p0+px
    for (int ch = 0; ch < 2; ch++) {
        __syncthreads();
        {   // build w chunk from centroids (L2-resident) + fold bias; 27 warps x 3 rows
            #pragma unroll
            for (int i = 0; i < 3; i++) {
                int P = wid * 3 + i;          // row = s*16 + kmg, 0..79
                if (P < 80) {
                    int s = P >> 4, kmg = P & 15;
                    const float* c0p = cent + ((32 * ch + kmg) * S1C + s) * CC;
                    const float* c1p = c0p + 80 * CC;   // k+16
                    float ssq0 = 0.f, ssq1 = 0.f;
                    #pragma unroll
                    for (int u = 0; u < 4; u++) {
                        int c = lane + 32 * u;
                        float a = c0p[c], b = c1p[c];
                        *(float2*)(ws + P * 256 + c * 2) =
                            make_float2(2.0f * ALPHA_C * a, 2.0f * ALPHA_C * b);
                        ssq0 += a * a;
                        ssq1 += b * b;
                    }
                    #pragma unroll
                    for (int o = 16; o; o >>= 1) {
                        ssq0 += __shfl_xor_sync(0xffffffffu, ssq0, o);
                        ssq1 += __shfl_xor_sync(0xffffffffu, ssq1, o);
                    }
                    if (lane == 0) {
                        bs[(ch * 80 + P) * 2 + 0] = -ALPHA_C * sqrtf(ssq0);
                        bs[(ch * 80 + P) * 2 + 1] = -ALPHA_C * sqrtf(ssq1);
                    }
                }
            }
        }
        __syncthreads();

        unsigned long long acc[5][2];
        #pragma unroll
        for (int s = 0; s < 5; s++) { acc[s][0] = 0ull; acc[s][1] = 0ull; }

        #pragma unroll 4
        for (int c2 = 0; c2 < 64; c2++) {
            // dense: warp reads contiguous 512 B (its pixel half)
            float4 xa = *(const float4*)(xs + c2 * 260 + ph * 128 + 4 * lane);
            // xa = {x0[p0], x1[p0], x0[p0+1], x1[p0+1]}
            unsigned long long xd0 = dup2(xa.x), xd1 = dup2(xa.y);   // px0: c even, odd
            unsigned long long xd2 = dup2(xa.z), xd3 = dup2(xa.w);   // px1
            #pragma unroll
            for (int s = 0; s < 5; s++) {
                ulonglong2 wv = *(const ulonglong2*)(ws + (s * 16 + mg) * 256 + c2 * 4);
                fma2(acc[s][0], wv.x, xd0); fma2(acc[s][0], wv.y, xd1);
                fma2(acc[s][1], wv.x, xd2); fma2(acc[s][1], wv.y, xd3);
            }
        }

        float b0[5], b1[5];
        #pragma unroll
        for (int s = 0; s < 5; s++) {
            b0[s] = bs[(ch * 80 + s * 16 + mg) * 2 + 0];
            b1[s] = bs[(ch * 80 + s * 16 + mg) * 2 + 1];
        }
        #pragma unroll
        for (int px = 0; px < 2; px++) {
            float lx[5], ly[5];
            #pragma unroll
            for (int s = 0; s < 5; s++) {
                float2 a = unpack2(acc[s][px]);
                lx[s] = a.x + b0[s];   // k2 = 0
                ly[s] = a.y + b1[s];   // k2 = 1
            }
            float m0 = fmaxf(fmaxf(fmaxf(lx[0], lx[1]), fmaxf(lx[2], lx[3])), lx[4]);
            float e0 = __expf(lx[0] - m0);
            float s0 = e0 + __expf(lx[1] - m0) + __expf(lx[2] - m0)
                          + __expf(lx[3] - m0) + __expf(lx[4] - m0);
            l0r[ch * 4 + px] = lx[0];
            btr[ch * 4 + px] = e0 * __frcp_rn(s0);
            float m1 = fmaxf(fmaxf(fmaxf(ly[0], ly[1]), fmaxf(ly[2], ly[3])), ly[4]);
            float e1 = __expf(ly[0] - m1);
            float s1 = e1 + __expf(ly[1] - m1) + __expf(ly[2] - m1)
                          + __expf(ly[3] - m1) + __expf(ly[4] - m1);
            l0r[ch * 4 + 2 + px] = ly[0];
            btr[ch * 4 + 2 + px] = e1 * __frcp_rn(s1);
        }
    }

    // ---- alpha softmax over k: cross-warp reduction via red[p][17] ----
    #pragma unroll
    for (int px = 0; px < 2; px++) {
        float mx = fmaxf(fmaxf(l0r[px], l0r[2 + px]), fmaxf(l0r[4 + px], l0r[6 + px]));
        red[(p0 + px) * 17 + mg] = mx;
    }
    __syncthreads();
    float amax[2];
    #pragma unroll
    for (int px = 0; px < 2; px++) {
        float m = -1e30f;
        #pragma unroll
        for (int i = 0; i < 16; i++) m = fmaxf(m, red[(p0 + px) * 17 + i]);
        amax[px] = m;
    }
    __syncthreads();
    #pragma unroll
    for (int px = 0; px < 2; px++) {
        float s = __expf(l0r[px] - amax[px]) + __expf(l0r[2 + px] - amax[px])
                + __expf(l0r[4 + px] - amax[px]) + __expf(l0r[6 + px] - amax[px]);
        red[(p0 + px) * 17 + mg] = s;
    }
    __syncthreads();
    float ainv[2];
    #pragma unroll
    for (int px = 0; px < 2; px++) {
        float s = 0.f;
        #pragma unroll
        for (int i = 0; i < 16; i++) s += red[(p0 + px) * 17 + i];
        ainv[px] = __frcp_rn(s);
    }

    // ---- w_assign to smem (alias over ws), soft_assign to gmem, sumw per (k, ph) ----
    #pragma unroll
    for (int ch = 0; ch < 2; ch++)
        #pragma unroll
        for (int k2 = 0; k2 < 2; k2++) {
            int k = ch * 32 + mg + k2 * 16;
            float sav[2], wa[2];
            float sw = 0.f;
            #pragma unroll
            for (int px = 0; px < 2; px++) {
                int idx = ch * 4 + k2 * 2 + px;
                float sa = __expf(l0r[idx] - amax[px]) * ainv[px] * btr[idx];
                float w = (p0 + px < pvalid) ? (1.0f + sa) : 0.0f;
                sav[px] = sa;
                wa[px] = w;
                sw += w;
            }
            *(float4*)(was + (k * 130 + p0) * 2) = make_float4(wa[0], wa[0], wa[1], wa[1]);
            if (p0 < pvalid)
                *(float2*)(sa_out + (n * KK + k) * PP + p0t + p0) = make_float2(sav[0], sav[1]);
            #pragma unroll
            for (int o = 16; o; o >>= 1) sw += __shfl_xor_sync(0xffffffffu, sw, o);
            if (lane == 0) g_sumw[bx * 128 + k * 2 + ph] = sw;
        }
    __syncthreads();

    // ---- phase 2: out_part[k][c] = sum over this warp's pixel half ----
    {
        int cg = lane, kg = mg, half = ph;
        unsigned long long a2[4][2];
        #pragma unroll
        for (int q = 0; q < 4; q++) { a2[q][0] = 0ull; a2[q][1] = 0ull; }
        int pbeg = half * 64;
        #pragma unroll 2
        for (int pi = 0; pi < 64; pi += 2) {
            int p = pbeg + pi;
            ulonglong2 xv0 = *(const ulonglong2*)(xs + (cg * 130 + p) * 2);
            ulonglong2 xv1 = *(const ulonglong2*)(xs + ((cg + 32) * 130 + p) * 2);
            #pragma unroll
            for (int q = 0; q < 4; q++) {
                ulonglong2 wv = *(const ulonglong2*)(was + ((kg * 4 + q) * 130 + p) * 2);
                fma2(a2[q][0], wv.x, xv0.x);
                fma2(a2[q][0], wv.y, xv0.y);
                fma2(a2[q][1], wv.x, xv1.x);
                fma2(a2[q][1], wv.y, xv1.y);
            }
        }
        float* pb = g_part + (bx * 2 + half) * 8192;
        #pragma unroll
        for (int q = 0; q < 4; q++) {
            int k = kg * 4 + q;
            #pragma unroll
            for (int j = 0; j < 2; j++) {
                int c2 = cg + 32 * j;
                float2 r = unpack2(a2[q][j]);
                *(float2*)(pb + k * 128 + c2 * 2) = r;
            }
        }
    }

    // ---- signal: this n's tile done ----
    __syncthreads();
    if (tid == 0) {
        __threadfence();
        atomicAdd(&g_cnt[n], 1);
    }

    if (bx >= 64) return;   // non-finalize blocks exit

    // ---- finalize: wait for n2's 16 tiles, reduce 32 slots, row norm, global 1/8 ----
    int n2 = bx >> 3, seg = bx & 7;
    if (tid == 0) {
        while (((volatile int*)g_cnt)[n2] < 16) __nanosleep(32);
        __threadfence();
    }
    __syncthreads();
    if (tid < 512) {
        int kl = tid >> 6, ci = tid & 63;         // 8 k-rows x 64 c-pairs
        int k = seg * 8 + kl, c0 = ci * 2;
        const float* pb = g_part + n2 * TILES * 2 * 8192 + k * 128 + c0;
        float a0 = 0.f, a1 = 0.f;
        #pragma unroll
        for (int t = 0; t < TILES * 2; t++) {
            float2 u = *(const float2*)(pb + t * 8192);
            a0 += u.x; a1 += u.y;
        }
        float sw = 0.f;
        const float* sb = g_sumw + n2 * TILES * 128 + k * 2;
        #pragma unroll
        for (int t = 0; t < TILES; t++) sw += sb[t * 128] + sb[t * 128 + 1];
        float2 rp = *(const float2*)(cent + k * (S1C * CC) + c0);
        float v0 = a0 - rp.x * sw;
        float v1 = a1 - rp.y * sw;
        float ssq = v0 * v0 + v1 * v1;
        #pragma unroll
        for (int o = 16; o; o >>= 1) ssq += __shfl_xor_sync(0xffffffffu, ssq, o);
        if ((tid & 31) == 0) red[kl * 2 + ((tid >> 5) & 1)] = ssq;
        __syncthreads();
        float tot = red[kl * 2] + red[kl * 2 + 1];
        float sc = 0.125f / fmaxf(sqrtf(tot), EPS_C);   // row norm * exact global 1/8
        *(float2*)(out + n2 * (KK * CC) + k * 128 + c0) = make_float2(v0 * sc, v1 * sc);
    } else {
        __syncthreads();
    }
    __syncthreads();
    if (tid == 0) {
        int old = atomicAdd(&g_cnt[n2], 1);   // -> 24 when all 8 finalize blocks done
        if (old == 23) {
            __threadfence();
            g_cnt[n2] = 0;                    // reset for next graph replay
        }
    }
}

extern "C" void kernel_launch(void* const* d_in, const int* in_sizes, int n_in,
                              void* d_out, int out_size) {
    const float* x    = (const float*)d_in[0];   // (8,128,44,44)
    const float* cent = (const float*)d_in[1];   // (64,5,128)
    float* out = (float*)d_out;                  // [flat (8,8192) | soft_assign (8,64,1,1936)]
    float* sa = out + NN * KK * CC;

    cudaFuncSetAttribute(main_kernel, cudaFuncAttributeMaxDynamicSharedMemorySize, 158464);
    main_kernel<<<NBLK, 1024, 158464>>>(x, cent, sa, out);
}

// round 17
// speedup vs baseline: 1.0228x; 1.0228x over previous
#include <cuda_runtime.h>

#define KK    64
#define S1C   5
#define CC    128
#define MM    320         // KK*S1C
#define PP    1936        // 44*44
#define NN    8
#define PT    128         // pixels per tile
#define TILES 16          // ceil(1936/128)
#define NBLK  128         // grid size (fully co-resident: 128 < 148 SMs)
#define ALPHA_C 1500.0f
#define EPS_C   1e-12f

// ---- device scratch (static: no allocations allowed) ----
__device__ float g_part[NN * TILES * KK * CC];  // per-tile partial accumulators (4.2 MB)
__device__ float g_sumw[NN * TILES * KK];
__device__ int g_cnt[NN];                       // per-n progress: 16 tiles -> 24 finalize -> reset 0

// ---- f32x2 helpers (ptxas never auto-emits FFMA2) ----
__device__ __forceinline__ unsigned long long dup2(float v) {
    unsigned long long r;
    asm("mov.b64 %0, {%1, %1};" : "=l"(r) : "f"(v));
    return r;
}
__device__ __forceinline__ void fma2(unsigned long long& d, unsigned long long a, unsigned long long b) {
    asm("fma.rn.f32x2 %0, %1, %2, %0;" : "+l"(d) : "l"(a), "l"(b));
}
__device__ __forceinline__ float2 unpack2(unsigned long long v) {
    float2 r;
    asm("mov.b64 {%0, %1}, %2;" : "=f"(r.x), "=f"(r.y) : "l"(v));
    return r;
}

// ======================= single fused kernel =======================
// block = (n, pixel-tile of 128), 128 blocks = 1 co-resident wave, 512 threads. smem 158464 B:
//   xs : [64 c2][130 p][2]  pairs {x[2c2][p], x[2c2+1][p]}    66560 B
//   ws : 80 pairs x 256     one 80 KB w chunk / was alias     81920 B
//   red: [128 p][17]        cross-warp alpha reduction         8704 B
//   bs : float[320]         biases                             1280 B
__global__ __launch_bounds__(512, 1)
void main_kernel(const float* __restrict__ x, const float* __restrict__ cent,
                 float* __restrict__ sa_out, float* __restrict__ out) {
    extern __shared__ float smem[];
    float* xs  = smem;                    // 16640 floats
    float* ws  = smem + 16640;            // 20480 floats (alias: was 64x130x2 = 16640)
    float* red = smem + 16640 + 20480;    // 2176 floats
    float* bs  = red + 2176;              // 320 floats
    float* was = ws;

    int tid = threadIdx.x;
    int lane = tid & 31;
    int mg = tid >> 5;      // warp id = k-pair base within chunk
    int bx = blockIdx.x;
    int n = bx >> 4, tile = bx & 15;
    int p0 = tile * PT;
    int pvalid = min(PT, PP - p0);   // 128, or 16 on tile 15

    // this thread's 4 pixels (dense-LDS mapping): {2l, 2l+1, 64+2l, 65+2l}
    int pA = 2 * lane;        // pixels pA, pA+1  (streams px=0,1)
    int pB = 64 + 2 * lane;   // pixels pB, pB+1  (streams px=2,3)

    // ---- load x tile: pair-interleave in registers, STS.128 stores ----
    {
        int r = tid >> 3;            // c2 row (64 rows)
        int seg = (tid & 7) * 16;    // pixel segment
        const float* s0 = x + (n * CC + 2 * r) * PP + p0 + seg;
        const float* s1 = s0 + PP;
        bool ok = seg < pvalid;
        #pragma unroll
        for (int i = 0; i < 4; i++) {
            float4 a = ok ? *(const float4*)(s0 + i * 4) : make_float4(0.f, 0.f, 0.f, 0.f);
            float4 b = ok ? *(const float4*)(s1 + i * 4) : make_float4(0.f, 0.f, 0.f, 0.f);
            float* d = xs + (r * 130 + seg + i * 4) * 2;
            *(float4*)(d)     = make_float4(a.x, b.x, a.y, b.y);
            *(float4*)(d + 4) = make_float4(a.z, b.z, a.w, b.w);
        }
    }

    // ---- phase 1: logits GEMM (2 chunks of 32 k x 5 s) + register softmax over s ----
    float l0r[16], btr[16];   // idx = ch*8 + k2*4 + px ; k = ch*32 + mg + k2*16
    for (int ch = 0; ch < 2; ch++) {
        __syncthreads();
        {   // build w chunk from centroids (L2-resident) + fold bias (ssq of same loads)
            #pragma unroll
            for (int i = 0; i < 5; i++) {
                int P = mg * 5 + i;           // row index = s*16 + kmg, 0..79
                int s = P >> 4, kmg = P & 15;
                const float* c0p = cent + ((32 * ch + kmg) * S1C + s) * CC;
                const float* c1p = c0p + 80 * CC;   // k+16
                float ssq0 = 0.f, ssq1 = 0.f;
                #pragma unroll
                for (int u = 0; u < 4; u++) {
                    int c = lane + 32 * u;
                    float a = c0p[c], b = c1p[c];
                    *(float2*)(ws + P * 256 + c * 2) =
                        make_float2(2.0f * ALPHA_C * a, 2.0f * ALPHA_C * b);
                    ssq0 += a * a;
                    ssq1 += b * b;
                }
                #pragma unroll
                for (int o = 16; o; o >>= 1) {
                    ssq0 += __shfl_xor_sync(0xffffffffu, ssq0, o);
                    ssq1 += __shfl_xor_sync(0xffffffffu, ssq1, o);
                }
                if (lane == 0) {
                    bs[(ch * 80 + P) * 2 + 0] = -ALPHA_C * sqrtf(ssq0);
                    bs[(ch * 80 + P) * 2 + 1] = -ALPHA_C * sqrtf(ssq1);
                }
            }
        }
        __syncthreads();

        unsigned long long acc[5][4];
        #pragma unroll
        for (int s = 0; s < 5; s++)
            #pragma unroll
            for (int q = 0; q < 4; q++) acc[s][q] = 0ull;

        // explicit x double-buffer: load iteration i+1 before consuming i
        float4 xa = *(const float4*)(xs + 4 * lane);
        float4 xb = *(const float4*)(xs + 128 + 4 * lane);
        #pragma unroll 4
        for (int c2 = 0; c2 < 64; c2++) {
            // prefetch next c2 (last iter reads harmlessly into ws region, value unused)
            const float* nrow = xs + (c2 + 1) * 260;
            float4 na = *(const float4*)(nrow + 4 * lane);
            float4 nb = *(const float4*)(nrow + 128 + 4 * lane);
            unsigned long long xd0 = dup2(xa.x), xd1 = dup2(xa.y);   // px0: c even, odd
            unsigned long long xd2 = dup2(xa.z), xd3 = dup2(xa.w);   // px1
            unsigned long long xd4 = dup2(xb.x), xd5 = dup2(xb.y);   // px2
            unsigned long long xd6 = dup2(xb.z), xd7 = dup2(xb.w);   // px3
            #pragma unroll
            for (int s = 0; s < 5; s++) {
                ulonglong2 wv = *(const ulonglong2*)(ws + (s * 16 + mg) * 256 + c2 * 4);
                fma2(acc[s][0], wv.x, xd0); fma2(acc[s][0], wv.y, xd1);
                fma2(acc[s][1], wv.x, xd2); fma2(acc[s][1], wv.y, xd3);
                fma2(acc[s][2], wv.x, xd4); fma2(acc[s][2], wv.y, xd5);
                fma2(acc[s][3], wv.x, xd6); fma2(acc[s][3], wv.y, xd7);
            }
            xa = na; xb = nb;
        }

        float b0[5], b1[5];
        #pragma unroll
        for (int s = 0; s < 5; s++) {
            b0[s] = bs[(ch * 80 + s * 16 + mg) * 2 + 0];
            b1[s] = bs[(ch * 80 + s * 16 + mg) * 2 + 1];
        }
        #pragma unroll
        for (int px = 0; px < 4; px++) {
            float lx[5], ly[5];
            #pragma unroll
            for (int s = 0; s < 5; s++) {
                float2 a = unpack2(acc[s][px]);
                lx[s] = a.x + b0[s];
                ly[s] = a.y + b1[s];
            }
            float m0 = fmaxf(fmaxf(fmaxf(lx[0], lx[1]), fmaxf(lx[2], lx[3])), lx[4]);
            float e0 = __expf(lx[0] - m0);
            float s0 = e0 + __expf(lx[1] - m0) + __expf(lx[2] - m0)
                          + __expf(lx[3] - m0) + __expf(lx[4] - m0);
            l0r[ch * 8 + px] = lx[0];
            btr[ch * 8 + px] = e0 * __frcp_rn(s0);
            float m1 = fmaxf(fmaxf(fmaxf(ly[0], ly[1]), fmaxf(ly[2], ly[3])), ly[4]);
            float e1 = __expf(ly[0] - m1);
            float s1 = e1 + __expf(ly[1] - m1) + __expf(ly[2] - m1)
                          + __expf(ly[3] - m1) + __expf(ly[4] - m1);
            l0r[ch * 8 + 4 + px] = ly[0];
            btr[ch * 8 + 4 + px] = e1 * __frcp_rn(s1);
        }
    }

    // pixel id per stream px: {pA, pA+1, pB, pB+1}
    int pix[4] = {pA, pA + 1, pB, pB + 1};

    // ---- alpha softmax over k: cross-warp reduction via red[p][17] ----
    #pragma unroll
    for (int px = 0; px < 4; px++) {
        float mx = fmaxf(fmaxf(l0r[px], l0r[4 + px]), fmaxf(l0r[8 + px], l0r[12 + px]));
        red[pix[px] * 17 + mg] = mx;
    }
    __syncthreads();
    float amax[4];
    #pragma unroll
    for (int px = 0; px < 4; px++) {
        float m = -1e30f;
        #pragma unroll
        for (int i = 0; i < 16; i++) m = fmaxf(m, red[pix[px] * 17 + i]);
        amax[px] = m;
    }
    __syncthreads();
    #pragma unroll
    for (int px = 0; px < 4; px++) {
        float s = __expf(l0r[px] - amax[px]) + __expf(l0r[4 + px] - amax[px])
                + __expf(l0r[8 + px] - amax[px]) + __expf(l0r[12 + px] - amax[px]);
        red[pix[px] * 17 + mg] = s;
    }
    __syncthreads();
    float ainv[4];
    #pragma unroll
    for (int px = 0; px < 4; px++) {
        float s = 0.f;
        #pragma unroll
        for (int i = 0; i < 16; i++) s += red[pix[px] * 17 + i];
        ainv[px] = __frcp_rn(s);
    }

    // ---- w_assign to smem (alias over ws, dense STS.128), soft_assign to gmem, sumw ----
    #pragma unroll
    for (int ch = 0; ch < 2; ch++)
        #pragma unroll
        for (int k2 = 0; k2 < 2; k2++) {
            int k = ch * 32 + mg + k2 * 16;
            float sav[4];
            float wa[4];
            float sw = 0.f;
            #pragma unroll
            for (int px = 0; px < 4; px++) {
                int idx = ch * 8 + k2 * 4 + px;
                float sa = __expf(l0r[idx] - amax[px]) * ainv[px] * btr[idx];
                float w = (pix[px] < pvalid) ? (1.0f + sa) : 0.0f;
                sav[px] = sa;
                wa[px] = w;
                sw += w;
            }
            *(float4*)(was + (k * 130 + pA) * 2) = make_float4(wa[0], wa[0], wa[1], wa[1]);
            *(float4*)(was + (k * 130 + pB) * 2) = make_float4(wa[2], wa[2], wa[3], wa[3]);
            float* sd = sa_out + (n * KK + k) * PP + p0;
            if (pA < pvalid) *(float2*)(sd + pA) = make_float2(sav[0], sav[1]);
            if (pB < pvalid) *(float2*)(sd + pB) = make_float2(sav[2], sav[3]);
            #pragma unroll
            for (int o = 16; o; o >>= 1) sw += __shfl_xor_sync(0xffffffffu, sw, o);
            if (lane == 0) g_sumw[bx * 64 + k] = sw;
        }
    __syncthreads();

    // ---- phase 2: out_part[k][c] = sum_p wa[k][p] * x[c][p] (x double-buffered) ----
    {
        int cg = lane, kg = mg;   // k = kg*4+q ; c2 = cg and cg+32
        unsigned long long a2[4][2];
        #pragma unroll
        for (int q = 0; q < 4; q++) { a2[q][0] = 0ull; a2[q][1] = 0ull; }
        ulonglong2 xv0 = *(const ulonglong2*)(xs + (cg * 130) * 2);
        ulonglong2 xv1 = *(const ulonglong2*)(xs + ((cg + 32) * 130) * 2);
        #pragma unroll 2
        for (int p = 0; p < PT; p += 2) {
            // prefetch next p (p=64 phantom read stays inside xs: (63*130+64)*2 < 16640)
            ulonglong2 nv0 = *(const ulonglong2*)(xs + (cg * 130 + p + 2) * 2);
            ulonglong2 nv1 = *(const ulonglong2*)(xs + ((cg + 32) * 130 + p + 2) * 2);
            #pragma unroll
            for (int q = 0; q < 4; q++) {
                ulonglong2 wv = *(const ulonglong2*)(was + ((kg * 4 + q) * 130 + p) * 2);
                fma2(a2[q][0], wv.x, xv0.x);
                fma2(a2[q][0], wv.y, xv0.y);
                fma2(a2[q][1], wv.x, xv1.x);
                fma2(a2[q][1], wv.y, xv1.y);
            }
            xv0 = nv0; xv1 = nv1;
        }
        float* pb = g_part + bx * 8192;
        #pragma unroll
        for (int q = 0; q < 4; q++) {
            int k = kg * 4 + q;
            #pragma unroll
            for (int j = 0; j < 2; j++) {
                int c2 = cg + 32 * j;
                float2 r = unpack2(a2[q][j]);
                *(float2*)(pb + k * 128 + c2 * 2) = r;
            }
        }
    }

    // ---- signal: this n's tile done ----
    __syncthreads();
    if (tid == 0) {
        __threadfence();
        atomicAdd(&g_cnt[n], 1);
    }

    if (bx >= 64) return;   // non-finalize blocks exit

    // ---- finalize: wait for n2's 16 tiles, tile-reduce, row norm, exact global 1/8 ----
    int n2 = bx >> 3, seg = bx & 7;
    if (tid == 0) {
        while (((volatile int*)g_cnt)[n2] < 16) __nanosleep(32);
        __threadfence();
    }
    __syncthreads();
    {
        int kl = tid >> 6, ci = tid & 63;         // 8 k-rows x 64 c-pairs
        int k = seg * 8 + kl, c0 = ci * 2;
        const float* pb = g_part + n2 * TILES * 8192 + k * 128 + c0;
        float a0 = 0.f, a1 = 0.f;
        #pragma unroll
        for (int t = 0; t < TILES; t++) {
            float2 u = *(const float2*)(pb + t * 8192);
            a0 += u.x; a1 += u.y;
        }
        float sw = 0.f;
        const float* sb = g_sumw + n2 * TILES * 64 + k;
        #pragma unroll
        for (int t = 0; t < TILES; t++) sw += sb[t * 64];
        float2 rp = *(const float2*)(cent + k * (S1C * CC) + c0);
        float v0 = a0 - rp.x * sw;
        float v1 = a1 - rp.y * sw;
        float ssq = v0 * v0 + v1 * v1;
        #pragma unroll
        for (int o = 16; o; o >>= 1) ssq += __shfl_xor_sync(0xffffffffu, ssq, o);
        if ((tid & 31) == 0) red[kl * 2 + ((tid >> 5) & 1)] = ssq;
        __syncthreads();
        float tot = red[kl * 2] + red[kl * 2 + 1];
        float sc = 0.125f / fmaxf(sqrtf(tot), EPS_C);   // row norm * exact global 1/8
        *(float2*)(out + n2 * (KK * CC) + k * 128 + c0) = make_float2(v0 * sc, v1 * sc);
    }
    __syncthreads();
    if (tid == 0) {
        int old = atomicAdd(&g_cnt[n2], 1);   // -> 24 when all 8 finalize blocks done
        if (old == 23) {
            __threadfence();
            g_cnt[n2] = 0;                    // reset for next graph replay
        }
    }
}

extern "C" void kernel_launch(void* const* d_in, const int* in_sizes, int n_in,
                              void* d_out, int out_size) {
    const float* x    = (const float*)d_in[0];   // (8,128,44,44)
    const float* cent = (const float*)d_in[1];   // (64,5,128)
    float* out = (float*)d_out;                  // [flat (8,8192) | soft_assign (8,64,1,1936)]
    float* sa = out + NN * KK * CC;

    cudaFuncSetAttribute(main_kernel, cudaFuncAttributeMaxDynamicSharedMemorySize, 158464);
    main_kernel<<<NBLK, 512, 158464>>>(x, cent, sa, out);
}